// round 16
// baseline (speedup 1.0000x reference)
#include <cuda_runtime.h>
#include <cuda_fp16.h>
#include <cstdint>

#define NNODES 100000
#define FIN    128
#define FHID   64
#define MHID   128
#define ELLW   96

__device__ int    g_cnt[NNODES];
__device__ __align__(16) int g_ell[(size_t)NNODES * ELLW];
__device__ __align__(16) __half g_hs[NNODES * FHID];     // layer1 gemm out, pre-scaled
__device__ __align__(16) __half g_bufC[NNODES * FHID];   // layer2 gemm out, pre-scaled
__device__ __align__(16) __half g_P[(size_t)NNODES * MHID];
__device__ __align__(16) __half g_Q[(size_t)NNODES * MHID];
// transposed fp16 weights: [n][k]
__device__ __align__(16) __half g_W1t[64 * 128];
__device__ __align__(16) __half g_W2t[64 * 64];
__device__ __align__(16) __half g_WPQt[256 * 64];

__device__ __forceinline__ __half2 h2(unsigned u) { return *reinterpret_cast<__half2*>(&u); }

__device__ __forceinline__ float4 unpack_h4(uint2 u) {
    float2 a = __half22float2(h2(u.x));
    float2 b = __half22float2(h2(u.y));
    return make_float4(a.x, a.y, b.x, b.y);
}

__device__ __forceinline__ void mma16816(float d[4],
                                         unsigned a0, unsigned a1, unsigned a2, unsigned a3,
                                         unsigned b0, unsigned b1) {
    asm volatile("mma.sync.aligned.m16n8k16.row.col.f32.f16.f16.f32 "
                 "{%0,%1,%2,%3}, {%4,%5,%6,%7}, {%8,%9}, {%0,%1,%2,%3};"
                 : "+f"(d[0]), "+f"(d[1]), "+f"(d[2]), "+f"(d[3])
                 : "r"(a0), "r"(a1), "r"(a2), "r"(a3), "r"(b0), "r"(b1));
}

__device__ __forceinline__ void st_h4(__half* p, float4 v) {
    __half2 lo = __floats2half2_rn(v.x, v.y);
    __half2 hi = __floats2half2_rn(v.z, v.w);
    uint2 u;
    u.x = *reinterpret_cast<unsigned*>(&lo);
    u.y = *reinterpret_cast<unsigned*>(&hi);
    *reinterpret_cast<uint2*>(p) = u;
}

// ---- shared agg core: 16 lanes/node, fp16 pair trees ----
// returns dinv*(self + sum neighbors) + bias (optionally relu'd), and rawcnt
template <int DO_RELU>
__device__ __forceinline__ float4 agg_node(const uint2* hs, int v, int l,
                                           const float* bias, int& rawcnt) {
    rawcnt = g_cnt[v];
    int cnt = min(rawcnt, ELLW);
    const int4* ep4 = reinterpret_cast<const int4*>(&g_ell[(size_t)v * ELLW]);

    float4 acc = unpack_h4(hs[(size_t)v * 16 + l]);
    float4 acc2 = make_float4(0.f, 0.f, 0.f, 0.f);
    int n = 0;
    for (; n + 8 <= cnt; n += 8) {
        int4 sa = ep4[(n >> 2)];
        int4 sb = ep4[(n >> 2) + 1];
        uint2 u0 = hs[(size_t)sa.x * 16 + l];
        uint2 u1 = hs[(size_t)sa.y * 16 + l];
        uint2 u2 = hs[(size_t)sa.z * 16 + l];
        uint2 u3 = hs[(size_t)sa.w * 16 + l];
        uint2 u4 = hs[(size_t)sb.x * 16 + l];
        uint2 u5 = hs[(size_t)sb.y * 16 + l];
        uint2 u6 = hs[(size_t)sb.z * 16 + l];
        uint2 u7 = hs[(size_t)sb.w * 16 + l];
        __half2 lo01 = __hadd2(h2(u0.x), h2(u1.x)), hi01 = __hadd2(h2(u0.y), h2(u1.y));
        __half2 lo23 = __hadd2(h2(u2.x), h2(u3.x)), hi23 = __hadd2(h2(u2.y), h2(u3.y));
        __half2 lo45 = __hadd2(h2(u4.x), h2(u5.x)), hi45 = __hadd2(h2(u4.y), h2(u5.y));
        __half2 lo67 = __hadd2(h2(u6.x), h2(u7.x)), hi67 = __hadd2(h2(u6.y), h2(u7.y));
        __half2 loA = __hadd2(lo01, lo23), hiA = __hadd2(hi01, hi23);
        __half2 loB = __hadd2(lo45, lo67), hiB = __hadd2(hi45, hi67);
        float2 a0 = __half22float2(loA), a1 = __half22float2(hiA);
        float2 b0 = __half22float2(loB), b1 = __half22float2(hiB);
        acc.x  += a0.x; acc.y  += a0.y; acc.z  += a1.x; acc.w  += a1.y;
        acc2.x += b0.x; acc2.y += b0.y; acc2.z += b1.x; acc2.w += b1.y;
    }
    if (n + 4 <= cnt) {
        int4 sa = ep4[(n >> 2)];
        uint2 u0 = hs[(size_t)sa.x * 16 + l];
        uint2 u1 = hs[(size_t)sa.y * 16 + l];
        uint2 u2 = hs[(size_t)sa.z * 16 + l];
        uint2 u3 = hs[(size_t)sa.w * 16 + l];
        __half2 lo01 = __hadd2(h2(u0.x), h2(u1.x)), hi01 = __hadd2(h2(u0.y), h2(u1.y));
        __half2 lo23 = __hadd2(h2(u2.x), h2(u3.x)), hi23 = __hadd2(h2(u2.y), h2(u3.y));
        __half2 loA = __hadd2(lo01, lo23), hiA = __hadd2(hi01, hi23);
        float2 a0 = __half22float2(loA), a1 = __half22float2(hiA);
        acc.x += a0.x; acc.y += a0.y; acc.z += a1.x; acc.w += a1.y;
        n += 4;
    }
    const int* ep = &g_ell[(size_t)v * ELLW];
    for (; n < cnt; n++) {
        float4 b0 = unpack_h4(hs[(size_t)ep[n] * 16 + l]);
        acc.x += b0.x; acc.y += b0.y; acc.z += b0.z; acc.w += b0.w;
    }
    acc.x += acc2.x; acc.y += acc2.y; acc.z += acc2.z; acc.w += acc2.w;
    float dv = rsqrtf((float)(rawcnt + 1));
    float4 bb = reinterpret_cast<const float4*>(bias)[l];
    float4 r;
    r.x = fmaf(dv, acc.x, bb.x);
    r.y = fmaf(dv, acc.y, bb.y);
    r.z = fmaf(dv, acc.z, bb.z);
    r.w = fmaf(dv, acc.w, bb.w);
    if (DO_RELU) {
        r.x = fmaxf(r.x, 0.f); r.y = fmaxf(r.y, 0.f);
        r.z = fmaxf(r.z, 0.f); r.w = fmaxf(r.w, 0.f);
    }
    return r;
}

// ---- setup: zero counts + convert/transpose weights ----
__global__ void k_setup(const float* __restrict__ W1, const float* __restrict__ W2,
                        const float* __restrict__ fc1W) {
    int i = blockIdx.x * blockDim.x + threadIdx.x;
    if (i < NNODES) g_cnt[i] = 0;
    if (i < 64 * 128) {
        int n = i >> 7, k = i & 127;
        g_W1t[i] = __float2half(W1[k * 64 + n]);
    } else if (i < 64 * 128 + 64 * 64) {
        int j = i - 64 * 128;
        int n = j >> 6, k = j & 63;
        g_W2t[j] = __float2half(W2[k * 64 + n]);
    } else if (i < 64 * 128 + 64 * 64 + 256 * 64) {
        int j = i - (64 * 128 + 64 * 64);
        int n = j >> 6, k = j & 63;
        float v = (n < 128) ? fc1W[k * MHID + n] : fc1W[(64 + k) * MHID + (n - 128)];
        g_WPQt[j] = __float2half(v);
    }
}

__global__ void k_fill(const int* __restrict__ src, const int* __restrict__ dst, int E) {
    int e = blockIdx.x * blockDim.x + threadIdx.x;
    if (e >= E) return;
    int s = src[e], d = dst[e];
    int pos = atomicAdd(&g_cnt[d], 1);
    if (pos < ELLW) g_ell[(size_t)d * ELLW + pos] = s;
}

// ---- GEMM1 (tensor core): g_hs = half((X[N,128] @ W1[128,64]) * dinv) ----
__global__ void __launch_bounds__(128) k_gemm1(const float* __restrict__ X) {
    __shared__ __half Xh[64][136];
    __shared__ __half Wh[64][136];
    const int tid = threadIdx.x;
    const int base = blockIdx.x * 64;

    #pragma unroll
    for (int it = 0; it < 8; it++) {
        int idx = tid + it * 128;
        int n = idx >> 4, c8 = idx & 15;
        *reinterpret_cast<uint4*>(&Wh[n][c8 * 8]) = reinterpret_cast<const uint4*>(g_W1t)[idx];
    }
    #pragma unroll
    for (int it = 0; it < 16; it++) {
        int idx = tid + it * 128;
        int r = idx >> 5, c4 = idx & 31;
        int row = base + r;
        float4 v = make_float4(0.f, 0.f, 0.f, 0.f);
        if (row < NNODES) v = reinterpret_cast<const float4*>(X)[(size_t)row * 32 + c4];
        st_h4(&Xh[r][c4 * 4], v);
    }
    __syncthreads();

    const int warp = tid >> 5, lane = tid & 31;
    const int quad = lane >> 2, tq = lane & 3;
    const int rbase = warp * 16;

    float acc[8][4];
    #pragma unroll
    for (int nt = 0; nt < 8; nt++)
        #pragma unroll
        for (int c = 0; c < 4; c++) acc[nt][c] = 0.f;

    #pragma unroll
    for (int kt = 0; kt < 8; kt++) {
        int k0 = kt * 16;
        unsigned a0 = *reinterpret_cast<const unsigned*>(&Xh[rbase + quad][k0 + tq * 2]);
        unsigned a1 = *reinterpret_cast<const unsigned*>(&Xh[rbase + quad + 8][k0 + tq * 2]);
        unsigned a2 = *reinterpret_cast<const unsigned*>(&Xh[rbase + quad][k0 + 8 + tq * 2]);
        unsigned a3 = *reinterpret_cast<const unsigned*>(&Xh[rbase + quad + 8][k0 + 8 + tq * 2]);
        #pragma unroll
        for (int nt = 0; nt < 8; nt++) {
            unsigned b0 = *reinterpret_cast<const unsigned*>(&Wh[nt * 8 + quad][k0 + tq * 2]);
            unsigned b1 = *reinterpret_cast<const unsigned*>(&Wh[nt * 8 + quad][k0 + 8 + tq * 2]);
            mma16816(acc[nt], a0, a1, a2, a3, b0, b1);
        }
    }

    int r0 = base + rbase + quad;
    int r1 = r0 + 8;
    float d0 = (r0 < NNODES) ? rsqrtf((float)(g_cnt[r0] + 1)) : 0.f;
    float d1 = (r1 < NNODES) ? rsqrtf((float)(g_cnt[r1] + 1)) : 0.f;
    #pragma unroll
    for (int nt = 0; nt < 8; nt++) {
        int n = nt * 8 + tq * 2;
        if (r0 < NNODES) {
            __half2 h = __floats2half2_rn(acc[nt][0] * d0, acc[nt][1] * d0);
            *reinterpret_cast<__half2*>(&g_hs[(size_t)r0 * 64 + n]) = h;
        }
        if (r1 < NNODES) {
            __half2 h = __floats2half2_rn(acc[nt][2] * d1, acc[nt][3] * d1);
            *reinterpret_cast<__half2*>(&g_hs[(size_t)r1 * 64 + n]) = h;
        }
    }
}

// ---- fused: agg1(+relu) -> GEMM2 -> dinv scale -> g_bufC (prescaled hs2) ----
// 256 threads = 16 nodes/block; NNODES = 6250*16 exact
__global__ void __launch_bounds__(256) k_fuse12(const float* __restrict__ b1) {
    __shared__ __half Wh[64][72];   // W2t
    __shared__ __half Xh[16][72];   // h1 tile (fp16)
    __shared__ float sdinv[16];
    const int tid = threadIdx.x;
    const int base = blockIdx.x * 16;

    #pragma unroll
    for (int it = 0; it < 2; it++) {
        int idx = tid + it * 256;       // 512 uint4
        int n = idx >> 3, c8 = idx & 7;
        *reinterpret_cast<uint4*>(&Wh[n][c8 * 8]) = reinterpret_cast<const uint4*>(g_W2t)[idx];
    }

    const int nl = tid >> 4;            // node within block
    const int l  = tid & 15;
    int rawcnt;
    float4 r = agg_node<1>(reinterpret_cast<const uint2*>(g_hs), base + nl, l, b1, rawcnt);
    st_h4(&Xh[nl][l * 4], r);
    if (l == 0) sdinv[nl] = rsqrtf((float)(rawcnt + 1));
    __syncthreads();

    const int warp = tid >> 5, lane = tid & 31;
    const int quad = lane >> 2, tq = lane & 3;

    float acc[4] = {0.f, 0.f, 0.f, 0.f};
    #pragma unroll
    for (int kt = 0; kt < 4; kt++) {
        int k0 = kt * 16;
        unsigned a0 = *reinterpret_cast<const unsigned*>(&Xh[quad][k0 + tq * 2]);
        unsigned a1 = *reinterpret_cast<const unsigned*>(&Xh[quad + 8][k0 + tq * 2]);
        unsigned a2 = *reinterpret_cast<const unsigned*>(&Xh[quad][k0 + 8 + tq * 2]);
        unsigned a3 = *reinterpret_cast<const unsigned*>(&Xh[quad + 8][k0 + 8 + tq * 2]);
        unsigned b0 = *reinterpret_cast<const unsigned*>(&Wh[warp * 8 + quad][k0 + tq * 2]);
        unsigned b1 = *reinterpret_cast<const unsigned*>(&Wh[warp * 8 + quad][k0 + 8 + tq * 2]);
        mma16816(acc, a0, a1, a2, a3, b0, b1);
    }

    int r0 = base + quad;
    int r1 = r0 + 8;
    float d0 = sdinv[quad];
    float d1 = sdinv[quad + 8];
    int n = warp * 8 + tq * 2;
    __half2 h0 = __floats2half2_rn(acc[0] * d0, acc[1] * d0);
    __half2 h1 = __floats2half2_rn(acc[2] * d1, acc[3] * d1);
    *reinterpret_cast<__half2*>(&g_bufC[(size_t)r0 * 64 + n]) = h0;
    *reinterpret_cast<__half2*>(&g_bufC[(size_t)r1 * 64 + n]) = h1;
}

// ---- fused: agg2 -> PQ GEMM -> g_P/g_Q ----
// 256 threads = 16 nodes/block
__global__ void __launch_bounds__(256) k_fusePQ(const float* __restrict__ b2,
                                                const float* __restrict__ fc1b) {
    __shared__ __half Wh[256][72];  // WPQt, 36 KB
    __shared__ __half Xh[16][72];   // out tile (fp16)
    const int tid = threadIdx.x;
    const int base = blockIdx.x * 16;

    #pragma unroll
    for (int it = 0; it < 8; it++) {
        int idx = tid + it * 256;       // 2048 uint4
        int n = idx >> 3, c8 = idx & 7;
        *reinterpret_cast<uint4*>(&Wh[n][c8 * 8]) = reinterpret_cast<const uint4*>(g_WPQt)[idx];
    }

    const int nl = tid >> 4;
    const int l  = tid & 15;
    int rawcnt;
    float4 r = agg_node<0>(reinterpret_cast<const uint2*>(g_bufC), base + nl, l, b2, rawcnt);
    st_h4(&Xh[nl][l * 4], r);
    __syncthreads();

    const int warp = tid >> 5, lane = tid & 31;
    const int quad = lane >> 2, tq = lane & 3;

    float acc[4][4];
    #pragma unroll
    for (int nt = 0; nt < 4; nt++)
        #pragma unroll
        for (int c = 0; c < 4; c++) acc[nt][c] = 0.f;

    #pragma unroll
    for (int kt = 0; kt < 4; kt++) {
        int k0 = kt * 16;
        unsigned a0 = *reinterpret_cast<const unsigned*>(&Xh[quad][k0 + tq * 2]);
        unsigned a1 = *reinterpret_cast<const unsigned*>(&Xh[quad + 8][k0 + tq * 2]);
        unsigned a2 = *reinterpret_cast<const unsigned*>(&Xh[quad][k0 + 8 + tq * 2]);
        unsigned a3 = *reinterpret_cast<const unsigned*>(&Xh[quad + 8][k0 + 8 + tq * 2]);
        #pragma unroll
        for (int nt = 0; nt < 4; nt++) {
            int nrow = warp * 32 + nt * 8 + quad;
            unsigned b0 = *reinterpret_cast<const unsigned*>(&Wh[nrow][k0 + tq * 2]);
            unsigned b1 = *reinterpret_cast<const unsigned*>(&Wh[nrow][k0 + 8 + tq * 2]);
            mma16816(acc[nt], a0, a1, a2, a3, b0, b1);
        }
    }

    int r0 = base + quad;
    int r1 = r0 + 8;
    #pragma unroll
    for (int nt = 0; nt < 4; nt++) {
        int ng = warp * 32 + nt * 8 + tq * 2;
        float bias0 = 0.f, bias1 = 0.f;
        if (ng < MHID) { bias0 = fc1b[ng]; bias1 = fc1b[ng + 1]; }
        __half2 h0 = __floats2half2_rn(acc[nt][0] + bias0, acc[nt][1] + bias1);
        __half2 h1 = __floats2half2_rn(acc[nt][2] + bias0, acc[nt][3] + bias1);
        if (ng < MHID) {
            *reinterpret_cast<__half2*>(&g_P[(size_t)r0 * MHID + ng]) = h0;
            *reinterpret_cast<__half2*>(&g_P[(size_t)r1 * MHID + ng]) = h1;
        } else {
            *reinterpret_cast<__half2*>(&g_Q[(size_t)r0 * MHID + (ng - MHID)]) = h0;
            *reinterpret_cast<__half2*>(&g_Q[(size_t)r1 * MHID + (ng - MHID)]) = h1;
        }
    }
}

// ---- query: res = relu(P[i] + Q[j]) @ fc2_W + fc2_b ----
// 8 lanes/query, 4 queries/warp, grid-stride with hoisted weights (R13 shape)
__global__ void __launch_bounds__(256) k_query(const int* __restrict__ qi,
                                               const int* __restrict__ qj,
                                               const float* __restrict__ fc2W,
                                               const float* __restrict__ fc2b,
                                               float* __restrict__ outp, int Q) {
    __shared__ float w2s[MHID * 2];
    int tid = threadIdx.x;
    w2s[tid] = fc2W[tid];
    __syncthreads();

    const int lane = tid & 31;
    const int sub  = lane >> 3;
    const int l    = lane & 7;
    const int c    = l * 16;
    float w0[16], w1[16];
    #pragma unroll
    for (int k = 0; k < 16; k++) {
        w0[k] = w2s[(c + k) * 2];
        w1[k] = w2s[(c + k) * 2 + 1];
    }
    const float bb0 = fc2b[0], bb1 = fc2b[1];
    const __half2 hz = __float2half2_rn(0.f);
    const uint4* P4 = reinterpret_cast<const uint4*>(g_P);
    const uint4* Q4 = reinterpret_cast<const uint4*>(g_Q);

    const int gwarp  = (blockIdx.x * blockDim.x + tid) >> 5;
    const int nwarps = (gridDim.x * blockDim.x) >> 5;

    for (int q = gwarp * 4 + sub; q < Q; q += nwarps * 4) {
        int i = qi[q];
        int j = qj[q];
        uint4 pa = P4[(size_t)i * 16 + 2 * l];
        uint4 pb = P4[(size_t)i * 16 + 2 * l + 1];
        uint4 qa = Q4[(size_t)j * 16 + 2 * l];
        uint4 qb = Q4[(size_t)j * 16 + 2 * l + 1];

        __half2 s[8];
        s[0] = __hmax2(__hadd2(h2(pa.x), h2(qa.x)), hz);
        s[1] = __hmax2(__hadd2(h2(pa.y), h2(qa.y)), hz);
        s[2] = __hmax2(__hadd2(h2(pa.z), h2(qa.z)), hz);
        s[3] = __hmax2(__hadd2(h2(pa.w), h2(qa.w)), hz);
        s[4] = __hmax2(__hadd2(h2(pb.x), h2(qb.x)), hz);
        s[5] = __hmax2(__hadd2(h2(pb.y), h2(qb.y)), hz);
        s[6] = __hmax2(__hadd2(h2(pb.z), h2(qb.z)), hz);
        s[7] = __hmax2(__hadd2(h2(pb.w), h2(qb.w)), hz);

        float a0 = 0.f, a1 = 0.f;
        #pragma unroll
        for (int m = 0; m < 8; m++) {
            float2 f = __half22float2(s[m]);
            a0 = fmaf(f.x, w0[2 * m],     a0);
            a1 = fmaf(f.x, w1[2 * m],     a1);
            a0 = fmaf(f.y, w0[2 * m + 1], a0);
            a1 = fmaf(f.y, w1[2 * m + 1], a1);
        }

        #pragma unroll
        for (int off = 4; off > 0; off >>= 1) {
            a0 += __shfl_xor_sync(0xffffffffu, a0, off, 8);
            a1 += __shfl_xor_sync(0xffffffffu, a1, off, 8);
        }
        if (l == 0) {
            *reinterpret_cast<float2*>(&outp[(size_t)q * 2]) =
                make_float2(a0 + bb0, a1 + bb1);
        }
    }
}

extern "C" void kernel_launch(void* const* d_in, const int* in_sizes, int n_in,
                              void* d_out, int out_size) {
    const float* feature = (const float*)d_in[0];
    const int*   edges   = (const int*)  d_in[1];
    const int*   qi      = (const int*)  d_in[2];
    const int*   qj      = (const int*)  d_in[3];
    const float* W1      = (const float*)d_in[4];
    const float* b1      = (const float*)d_in[5];
    const float* W2      = (const float*)d_in[6];
    const float* b2      = (const float*)d_in[7];
    const float* fc1W    = (const float*)d_in[8];
    const float* fc1b    = (const float*)d_in[9];
    const float* fc2W    = (const float*)d_in[10];
    const float* fc2b    = (const float*)d_in[11];
    float* outp = (float*)d_out;

    const int E = in_sizes[1] / 2;
    const int Q = in_sizes[2];
    const int* es = edges;
    const int* ed = edges + E;

    k_setup<<<(NNODES + 255) / 256, 256>>>(W1, W2, fc1W);
    k_fill<<<(E + 255) / 256, 256>>>(es, ed, E);

    // layer 1 gemm (tensor core, prescaled fp16 out)
    k_gemm1<<<(NNODES + 63) / 64, 128>>>(feature);

    // fused agg1(+relu) + gemm2 + scale -> g_bufC
    k_fuse12<<<NNODES / 16, 256>>>(b1);

    // fused agg2 + PQ gemm -> g_P/g_Q
    k_fusePQ<<<NNODES / 16, 256>>>(b2, fc1b);

    // queries: persistent grid-stride, 4 queries/warp
    k_query<<<1184, 256>>>(qi, qj, fc2W, fc2b, outp, Q);
}

// round 17
// speedup vs baseline: 1.0560x; 1.0560x over previous
#include <cuda_runtime.h>
#include <cuda_fp16.h>
#include <cstdint>

#define NNODES 100000
#define FIN    128
#define FHID   64
#define MHID   128
#define ELLW   96

__device__ int    g_cnt[NNODES];
__device__ __align__(16) int g_ell[(size_t)NNODES * ELLW];
__device__ __align__(16) __half g_hs[NNODES * FHID];     // layer1 gemm out -> later layer2 agg out
__device__ __align__(16) __half g_bufC[NNODES * FHID];   // layer2 gemm out (prescaled hs2)
__device__ __align__(16) __half g_P[(size_t)NNODES * MHID];
__device__ __align__(16) __half g_Q[(size_t)NNODES * MHID];
// transposed fp16 weights: [n][k]
__device__ __align__(16) __half g_W1t[64 * 128];
__device__ __align__(16) __half g_W2t[64 * 64];
__device__ __align__(16) __half g_WPQt[256 * 64];

__device__ __forceinline__ __half2 h2(unsigned u) { return *reinterpret_cast<__half2*>(&u); }

__device__ __forceinline__ float4 unpack_h4(uint2 u) {
    float2 a = __half22float2(h2(u.x));
    float2 b = __half22float2(h2(u.y));
    return make_float4(a.x, a.y, b.x, b.y);
}

__device__ __forceinline__ void mma16816(float d[4],
                                         unsigned a0, unsigned a1, unsigned a2, unsigned a3,
                                         unsigned b0, unsigned b1) {
    asm volatile("mma.sync.aligned.m16n8k16.row.col.f32.f16.f16.f32 "
                 "{%0,%1,%2,%3}, {%4,%5,%6,%7}, {%8,%9}, {%0,%1,%2,%3};"
                 : "+f"(d[0]), "+f"(d[1]), "+f"(d[2]), "+f"(d[3])
                 : "r"(a0), "r"(a1), "r"(a2), "r"(a3), "r"(b0), "r"(b1));
}

__device__ __forceinline__ void st_h4(__half* p, float4 v) {
    __half2 lo = __floats2half2_rn(v.x, v.y);
    __half2 hi = __floats2half2_rn(v.z, v.w);
    uint2 u;
    u.x = *reinterpret_cast<unsigned*>(&lo);
    u.y = *reinterpret_cast<unsigned*>(&hi);
    *reinterpret_cast<uint2*>(p) = u;
}

// ---- shared agg core: 16 lanes/node, fp16 pair trees ----
template <int DO_RELU>
__device__ __forceinline__ float4 agg_node(const uint2* hs, int v, int l,
                                           const float* bias, int& rawcnt) {
    rawcnt = g_cnt[v];
    int cnt = min(rawcnt, ELLW);
    const int4* ep4 = reinterpret_cast<const int4*>(&g_ell[(size_t)v * ELLW]);

    float4 acc = unpack_h4(hs[(size_t)v * 16 + l]);
    float4 acc2 = make_float4(0.f, 0.f, 0.f, 0.f);
    int n = 0;
    for (; n + 8 <= cnt; n += 8) {
        int4 sa = ep4[(n >> 2)];
        int4 sb = ep4[(n >> 2) + 1];
        uint2 u0 = hs[(size_t)sa.x * 16 + l];
        uint2 u1 = hs[(size_t)sa.y * 16 + l];
        uint2 u2 = hs[(size_t)sa.z * 16 + l];
        uint2 u3 = hs[(size_t)sa.w * 16 + l];
        uint2 u4 = hs[(size_t)sb.x * 16 + l];
        uint2 u5 = hs[(size_t)sb.y * 16 + l];
        uint2 u6 = hs[(size_t)sb.z * 16 + l];
        uint2 u7 = hs[(size_t)sb.w * 16 + l];
        __half2 lo01 = __hadd2(h2(u0.x), h2(u1.x)), hi01 = __hadd2(h2(u0.y), h2(u1.y));
        __half2 lo23 = __hadd2(h2(u2.x), h2(u3.x)), hi23 = __hadd2(h2(u2.y), h2(u3.y));
        __half2 lo45 = __hadd2(h2(u4.x), h2(u5.x)), hi45 = __hadd2(h2(u4.y), h2(u5.y));
        __half2 lo67 = __hadd2(h2(u6.x), h2(u7.x)), hi67 = __hadd2(h2(u6.y), h2(u7.y));
        __half2 loA = __hadd2(lo01, lo23), hiA = __hadd2(hi01, hi23);
        __half2 loB = __hadd2(lo45, lo67), hiB = __hadd2(hi45, hi67);
        float2 a0 = __half22float2(loA), a1 = __half22float2(hiA);
        float2 b0 = __half22float2(loB), b1 = __half22float2(hiB);
        acc.x  += a0.x; acc.y  += a0.y; acc.z  += a1.x; acc.w  += a1.y;
        acc2.x += b0.x; acc2.y += b0.y; acc2.z += b1.x; acc2.w += b1.y;
    }
    if (n + 4 <= cnt) {
        int4 sa = ep4[(n >> 2)];
        uint2 u0 = hs[(size_t)sa.x * 16 + l];
        uint2 u1 = hs[(size_t)sa.y * 16 + l];
        uint2 u2 = hs[(size_t)sa.z * 16 + l];
        uint2 u3 = hs[(size_t)sa.w * 16 + l];
        __half2 lo01 = __hadd2(h2(u0.x), h2(u1.x)), hi01 = __hadd2(h2(u0.y), h2(u1.y));
        __half2 lo23 = __hadd2(h2(u2.x), h2(u3.x)), hi23 = __hadd2(h2(u2.y), h2(u3.y));
        __half2 loA = __hadd2(lo01, lo23), hiA = __hadd2(hi01, hi23);
        float2 a0 = __half22float2(loA), a1 = __half22float2(hiA);
        acc.x += a0.x; acc.y += a0.y; acc.z += a1.x; acc.w += a1.y;
        n += 4;
    }
    const int* ep = &g_ell[(size_t)v * ELLW];
    for (; n < cnt; n++) {
        float4 b0 = unpack_h4(hs[(size_t)ep[n] * 16 + l]);
        acc.x += b0.x; acc.y += b0.y; acc.z += b0.z; acc.w += b0.w;
    }
    acc.x += acc2.x; acc.y += acc2.y; acc.z += acc2.z; acc.w += acc2.w;
    float dv = rsqrtf((float)(rawcnt + 1));
    float4 bb = reinterpret_cast<const float4*>(bias)[l];
    float4 r;
    r.x = fmaf(dv, acc.x, bb.x);
    r.y = fmaf(dv, acc.y, bb.y);
    r.z = fmaf(dv, acc.z, bb.z);
    r.w = fmaf(dv, acc.w, bb.w);
    if (DO_RELU) {
        r.x = fmaxf(r.x, 0.f); r.y = fmaxf(r.y, 0.f);
        r.z = fmaxf(r.z, 0.f); r.w = fmaxf(r.w, 0.f);
    }
    return r;
}

// ---- setup: zero counts + convert/transpose weights ----
__global__ void k_setup(const float* __restrict__ W1, const float* __restrict__ W2,
                        const float* __restrict__ fc1W) {
    int i = blockIdx.x * blockDim.x + threadIdx.x;
    if (i < NNODES) g_cnt[i] = 0;
    if (i < 64 * 128) {
        int n = i >> 7, k = i & 127;
        g_W1t[i] = __float2half(W1[k * 64 + n]);
    } else if (i < 64 * 128 + 64 * 64) {
        int j = i - 64 * 128;
        int n = j >> 6, k = j & 63;
        g_W2t[j] = __float2half(W2[k * 64 + n]);
    } else if (i < 64 * 128 + 64 * 64 + 256 * 64) {
        int j = i - (64 * 128 + 64 * 64);
        int n = j >> 6, k = j & 63;
        float v = (n < 128) ? fc1W[k * MHID + n] : fc1W[(64 + k) * MHID + (n - 128)];
        g_WPQt[j] = __float2half(v);
    }
}

__global__ void k_fill(const int* __restrict__ src, const int* __restrict__ dst, int E) {
    int e = blockIdx.x * blockDim.x + threadIdx.x;
    if (e >= E) return;
    int s = src[e], d = dst[e];
    int pos = atomicAdd(&g_cnt[d], 1);
    if (pos < ELLW) g_ell[(size_t)d * ELLW + pos] = s;
}

// ---- GEMM1 (tensor core): g_hs = half((X[N,128] @ W1[128,64]) * dinv) ----
__global__ void __launch_bounds__(128) k_gemm1(const float* __restrict__ X) {
    __shared__ __half Xh[64][136];
    __shared__ __half Wh[64][136];
    const int tid = threadIdx.x;
    const int base = blockIdx.x * 64;

    #pragma unroll
    for (int it = 0; it < 8; it++) {
        int idx = tid + it * 128;
        int n = idx >> 4, c8 = idx & 15;
        *reinterpret_cast<uint4*>(&Wh[n][c8 * 8]) = reinterpret_cast<const uint4*>(g_W1t)[idx];
    }
    #pragma unroll
    for (int it = 0; it < 16; it++) {
        int idx = tid + it * 128;
        int r = idx >> 5, c4 = idx & 31;
        int row = base + r;
        float4 v = make_float4(0.f, 0.f, 0.f, 0.f);
        if (row < NNODES) v = reinterpret_cast<const float4*>(X)[(size_t)row * 32 + c4];
        st_h4(&Xh[r][c4 * 4], v);
    }
    __syncthreads();

    const int warp = tid >> 5, lane = tid & 31;
    const int quad = lane >> 2, tq = lane & 3;
    const int rbase = warp * 16;

    float acc[8][4];
    #pragma unroll
    for (int nt = 0; nt < 8; nt++)
        #pragma unroll
        for (int c = 0; c < 4; c++) acc[nt][c] = 0.f;

    #pragma unroll
    for (int kt = 0; kt < 8; kt++) {
        int k0 = kt * 16;
        unsigned a0 = *reinterpret_cast<const unsigned*>(&Xh[rbase + quad][k0 + tq * 2]);
        unsigned a1 = *reinterpret_cast<const unsigned*>(&Xh[rbase + quad + 8][k0 + tq * 2]);
        unsigned a2 = *reinterpret_cast<const unsigned*>(&Xh[rbase + quad][k0 + 8 + tq * 2]);
        unsigned a3 = *reinterpret_cast<const unsigned*>(&Xh[rbase + quad + 8][k0 + 8 + tq * 2]);
        #pragma unroll
        for (int nt = 0; nt < 8; nt++) {
            unsigned b0 = *reinterpret_cast<const unsigned*>(&Wh[nt * 8 + quad][k0 + tq * 2]);
            unsigned b1 = *reinterpret_cast<const unsigned*>(&Wh[nt * 8 + quad][k0 + 8 + tq * 2]);
            mma16816(acc[nt], a0, a1, a2, a3, b0, b1);
        }
    }

    int r0 = base + rbase + quad;
    int r1 = r0 + 8;
    float d0 = (r0 < NNODES) ? rsqrtf((float)(g_cnt[r0] + 1)) : 0.f;
    float d1 = (r1 < NNODES) ? rsqrtf((float)(g_cnt[r1] + 1)) : 0.f;
    #pragma unroll
    for (int nt = 0; nt < 8; nt++) {
        int n = nt * 8 + tq * 2;
        if (r0 < NNODES) {
            __half2 h = __floats2half2_rn(acc[nt][0] * d0, acc[nt][1] * d0);
            *reinterpret_cast<__half2*>(&g_hs[(size_t)r0 * 64 + n]) = h;
        }
        if (r1 < NNODES) {
            __half2 h = __floats2half2_rn(acc[nt][2] * d1, acc[nt][3] * d1);
            *reinterpret_cast<__half2*>(&g_hs[(size_t)r1 * 64 + n]) = h;
        }
    }
}

// ---- fused: agg1(+relu) -> GEMM2 -> dinv scale -> g_bufC (prescaled hs2) ----
__global__ void __launch_bounds__(256) k_fuse12(const float* __restrict__ b1) {
    __shared__ __half Wh[64][72];   // W2t
    __shared__ __half Xh[16][72];   // h1 tile (fp16)
    __shared__ float sdinv[16];
    const int tid = threadIdx.x;
    const int base = blockIdx.x * 16;

    #pragma unroll
    for (int it = 0; it < 2; it++) {
        int idx = tid + it * 256;       // 512 uint4
        int n = idx >> 3, c8 = idx & 7;
        *reinterpret_cast<uint4*>(&Wh[n][c8 * 8]) = reinterpret_cast<const uint4*>(g_W2t)[idx];
    }

    const int nl = tid >> 4;
    const int l  = tid & 15;
    int rawcnt;
    float4 r = agg_node<1>(reinterpret_cast<const uint2*>(g_hs), base + nl, l, b1, rawcnt);
    st_h4(&Xh[nl][l * 4], r);
    if (l == 0) sdinv[nl] = rsqrtf((float)(rawcnt + 1));
    __syncthreads();

    const int warp = tid >> 5, lane = tid & 31;
    const int quad = lane >> 2, tq = lane & 3;

    float acc[4] = {0.f, 0.f, 0.f, 0.f};
    #pragma unroll
    for (int kt = 0; kt < 4; kt++) {
        int k0 = kt * 16;
        unsigned a0 = *reinterpret_cast<const unsigned*>(&Xh[quad][k0 + tq * 2]);
        unsigned a1 = *reinterpret_cast<const unsigned*>(&Xh[quad + 8][k0 + tq * 2]);
        unsigned a2 = *reinterpret_cast<const unsigned*>(&Xh[quad][k0 + 8 + tq * 2]);
        unsigned a3 = *reinterpret_cast<const unsigned*>(&Xh[quad + 8][k0 + 8 + tq * 2]);
        unsigned b0 = *reinterpret_cast<const unsigned*>(&Wh[warp * 8 + quad][k0 + tq * 2]);
        unsigned b1 = *reinterpret_cast<const unsigned*>(&Wh[warp * 8 + quad][k0 + 8 + tq * 2]);
        mma16816(acc, a0, a1, a2, a3, b0, b1);
    }

    int r0 = base + quad;
    int r1 = r0 + 8;
    float d0 = sdinv[quad];
    float d1 = sdinv[quad + 8];
    int n = warp * 8 + tq * 2;
    __half2 h0 = __floats2half2_rn(acc[0] * d0, acc[1] * d0);
    __half2 h1 = __floats2half2_rn(acc[2] * d1, acc[3] * d1);
    *reinterpret_cast<__half2*>(&g_bufC[(size_t)r0 * 64 + n]) = h0;
    *reinterpret_cast<__half2*>(&g_bufC[(size_t)r1 * 64 + n]) = h1;
}

// ---- agg2: out(g_hs) = dinv*(bufC[v] + sum bufC[u]) + b2  (fp16 out, no relu) ----
__global__ void __launch_bounds__(256) k_agg2(const float* __restrict__ b2) {
    int v = blockIdx.x * 16 + (threadIdx.x >> 4);
    int l = threadIdx.x & 15;
    if (v >= NNODES) return;
    int rawcnt;
    float4 r = agg_node<0>(reinterpret_cast<const uint2*>(g_bufC), v, l, b2, rawcnt);
    st_h4(&g_hs[(size_t)v * 64 + l * 4], r);
}

// ---- PQ GEMM (tensor core, M=64 tiles, 256 threads): [P|Q] = out @ WPQt^T ----
__global__ void __launch_bounds__(256) k_gemmPQ(const float* __restrict__ fc1b) {
    __shared__ __half Xh[64][72];    // 9 KB
    __shared__ __half Wh[256][72];   // 36 KB
    const int tid = threadIdx.x;
    const int base = blockIdx.x * 64;

    #pragma unroll
    for (int it = 0; it < 8; it++) {
        int idx = tid + it * 256;        // 2048 uint4
        int n = idx >> 3, c8 = idx & 7;
        *reinterpret_cast<uint4*>(&Wh[n][c8 * 8]) = reinterpret_cast<const uint4*>(g_WPQt)[idx];
    }
    #pragma unroll
    for (int it = 0; it < 2; it++) {
        int idx = tid + it * 256;        // 512 uint4 = 64 rows x 8
        int r = idx >> 3, c8 = idx & 7;
        int row = base + r;
        uint4 u = make_uint4(0u, 0u, 0u, 0u);
        if (row < NNODES) u = reinterpret_cast<const uint4*>(g_hs)[(size_t)row * 8 + c8];
        *reinterpret_cast<uint4*>(&Xh[r][c8 * 8]) = u;
    }
    __syncthreads();

    const int warp = tid >> 5, lane = tid & 31;
    const int quad = lane >> 2, tq = lane & 3;
    const int n0w = warp * 32;           // 8 warps x 32 cols = 256

    float acc[4][4][4];                  // [mt][nt][c]
    #pragma unroll
    for (int mt = 0; mt < 4; mt++)
        #pragma unroll
        for (int nt = 0; nt < 4; nt++)
            #pragma unroll
            for (int c = 0; c < 4; c++) acc[mt][nt][c] = 0.f;

    #pragma unroll
    for (int kt = 0; kt < 4; kt++) {
        int k0 = kt * 16;
        #pragma unroll
        for (int mt = 0; mt < 4; mt++) {
            int rb = mt * 16;
            unsigned a0 = *reinterpret_cast<const unsigned*>(&Xh[rb + quad][k0 + tq * 2]);
            unsigned a1 = *reinterpret_cast<const unsigned*>(&Xh[rb + quad + 8][k0 + tq * 2]);
            unsigned a2 = *reinterpret_cast<const unsigned*>(&Xh[rb + quad][k0 + 8 + tq * 2]);
            unsigned a3 = *reinterpret_cast<const unsigned*>(&Xh[rb + quad + 8][k0 + 8 + tq * 2]);
            #pragma unroll
            for (int nt = 0; nt < 4; nt++) {
                int nrow = n0w + nt * 8 + quad;
                unsigned b0 = *reinterpret_cast<const unsigned*>(&Wh[nrow][k0 + tq * 2]);
                unsigned b1 = *reinterpret_cast<const unsigned*>(&Wh[nrow][k0 + 8 + tq * 2]);
                mma16816(acc[mt][nt], a0, a1, a2, a3, b0, b1);
            }
        }
    }

    #pragma unroll
    for (int mt = 0; mt < 4; mt++) {
        int r0 = base + mt * 16 + quad;
        int r1 = r0 + 8;
        #pragma unroll
        for (int nt = 0; nt < 4; nt++) {
            int ng = n0w + nt * 8 + tq * 2;
            float bias0 = 0.f, bias1 = 0.f;
            if (ng < MHID) { bias0 = fc1b[ng]; bias1 = fc1b[ng + 1]; }
            __half2 h0 = __floats2half2_rn(acc[mt][nt][0] + bias0, acc[mt][nt][1] + bias1);
            __half2 h1 = __floats2half2_rn(acc[mt][nt][2] + bias0, acc[mt][nt][3] + bias1);
            if (ng < MHID) {
                if (r0 < NNODES) *reinterpret_cast<__half2*>(&g_P[(size_t)r0 * MHID + ng]) = h0;
                if (r1 < NNODES) *reinterpret_cast<__half2*>(&g_P[(size_t)r1 * MHID + ng]) = h1;
            } else {
                if (r0 < NNODES) *reinterpret_cast<__half2*>(&g_Q[(size_t)r0 * MHID + (ng - MHID)]) = h0;
                if (r1 < NNODES) *reinterpret_cast<__half2*>(&g_Q[(size_t)r1 * MHID + (ng - MHID)]) = h1;
            }
        }
    }
}

// ---- query: res = relu(P[i] + Q[j]) @ fc2_W + fc2_b ----
// 8 lanes/query, 4 queries/warp, grid-stride with hoisted weights (R13 shape)
__global__ void __launch_bounds__(256) k_query(const int* __restrict__ qi,
                                               const int* __restrict__ qj,
                                               const float* __restrict__ fc2W,
                                               const float* __restrict__ fc2b,
                                               float* __restrict__ outp, int Q) {
    __shared__ float w2s[MHID * 2];
    int tid = threadIdx.x;
    w2s[tid] = fc2W[tid];
    __syncthreads();

    const int lane = tid & 31;
    const int sub  = lane >> 3;
    const int l    = lane & 7;
    const int c    = l * 16;
    float w0[16], w1[16];
    #pragma unroll
    for (int k = 0; k < 16; k++) {
        w0[k] = w2s[(c + k) * 2];
        w1[k] = w2s[(c + k) * 2 + 1];
    }
    const float bb0 = fc2b[0], bb1 = fc2b[1];
    const __half2 hz = __float2half2_rn(0.f);
    const uint4* P4 = reinterpret_cast<const uint4*>(g_P);
    const uint4* Q4 = reinterpret_cast<const uint4*>(g_Q);

    const int gwarp  = (blockIdx.x * blockDim.x + tid) >> 5;
    const int nwarps = (gridDim.x * blockDim.x) >> 5;

    for (int q = gwarp * 4 + sub; q < Q; q += nwarps * 4) {
        int i = qi[q];
        int j = qj[q];
        uint4 pa = P4[(size_t)i * 16 + 2 * l];
        uint4 pb = P4[(size_t)i * 16 + 2 * l + 1];
        uint4 qa = Q4[(size_t)j * 16 + 2 * l];
        uint4 qb = Q4[(size_t)j * 16 + 2 * l + 1];

        __half2 s[8];
        s[0] = __hmax2(__hadd2(h2(pa.x), h2(qa.x)), hz);
        s[1] = __hmax2(__hadd2(h2(pa.y), h2(qa.y)), hz);
        s[2] = __hmax2(__hadd2(h2(pa.z), h2(qa.z)), hz);
        s[3] = __hmax2(__hadd2(h2(pa.w), h2(qa.w)), hz);
        s[4] = __hmax2(__hadd2(h2(pb.x), h2(qb.x)), hz);
        s[5] = __hmax2(__hadd2(h2(pb.y), h2(qb.y)), hz);
        s[6] = __hmax2(__hadd2(h2(pb.z), h2(qb.z)), hz);
        s[7] = __hmax2(__hadd2(h2(pb.w), h2(qb.w)), hz);

        float a0 = 0.f, a1 = 0.f;
        #pragma unroll
        for (int m = 0; m < 8; m++) {
            float2 f = __half22float2(s[m]);
            a0 = fmaf(f.x, w0[2 * m],     a0);
            a1 = fmaf(f.x, w1[2 * m],     a1);
            a0 = fmaf(f.y, w0[2 * m + 1], a0);
            a1 = fmaf(f.y, w1[2 * m + 1], a1);
        }

        #pragma unroll
        for (int off = 4; off > 0; off >>= 1) {
            a0 += __shfl_xor_sync(0xffffffffu, a0, off, 8);
            a1 += __shfl_xor_sync(0xffffffffu, a1, off, 8);
        }
        if (l == 0) {
            *reinterpret_cast<float2*>(&outp[(size_t)q * 2]) =
                make_float2(a0 + bb0, a1 + bb1);
        }
    }
}

extern "C" void kernel_launch(void* const* d_in, const int* in_sizes, int n_in,
                              void* d_out, int out_size) {
    const float* feature = (const float*)d_in[0];
    const int*   edges   = (const int*)  d_in[1];
    const int*   qi      = (const int*)  d_in[2];
    const int*   qj      = (const int*)  d_in[3];
    const float* W1      = (const float*)d_in[4];
    const float* b1      = (const float*)d_in[5];
    const float* W2      = (const float*)d_in[6];
    const float* b2      = (const float*)d_in[7];
    const float* fc1W    = (const float*)d_in[8];
    const float* fc1b    = (const float*)d_in[9];
    const float* fc2W    = (const float*)d_in[10];
    const float* fc2b    = (const float*)d_in[11];
    float* outp = (float*)d_out;

    const int E = in_sizes[1] / 2;
    const int Q = in_sizes[2];
    const int* es = edges;
    const int* ed = edges + E;

    k_setup<<<(NNODES + 255) / 256, 256>>>(W1, W2, fc1W);
    k_fill<<<(E + 255) / 256, 256>>>(es, ed, E);

    // layer 1 gemm (tensor core, prescaled fp16 out -> g_hs)
    k_gemm1<<<(NNODES + 63) / 64, 128>>>(feature);

    // fused agg1(+relu) + gemm2 + scale -> g_bufC
    k_fuse12<<<NNODES / 16, 256>>>(b1);

    // agg2 -> g_hs (fp16 "out" rows)
    k_agg2<<<NNODES / 16, 256>>>(b2);

    // PQ gemm (M=64 tiles) -> g_P/g_Q
    k_gemmPQ<<<(NNODES + 63) / 64, 256>>>(fc1b);

    // queries: persistent grid-stride, 4 queries/warp
    k_query<<<1184, 256>>>(qi, qj, fc2W, fc2b, outp, Q);
}